// round 10
// baseline (speedup 1.0000x reference)
#include <cuda_runtime.h>
#include <cuda_fp16.h>
#include <cstdint>

// R10: bisect round. R7 skeleton (fp32 inputs/outputs, same launcher) with
// conv-internal changes only: K-chunk 32 + ldmatrix.x4 fragment loads,
// fp16 packing done in fetch (overlapped with MMA).

#define BATCH 16
#define HIDC  512
#define HW    64
#define PIX   4096
#define NPIX  65536
#define FLAT  8320

// ---------------- scratch (static device globals) ---------------------------
__device__ float g_act1[(size_t)BATCH*HIDC*PIX];   // 128 MiB
__device__ float g_act2[(size_t)BATCH*HIDC*PIX];   // 128 MiB
__device__ float g_feat[BATCH*FLAT];
__device__ float g_h1[BATCH*512];
__device__ float g_h2[BATCH*256];
__device__ float g_g1[BATCH*256];
__device__ float g_pm[BATCH*12];
__device__ float g_ls[BATCH*12];

// ---------------- helpers ----------------------------------------------------
__device__ __forceinline__ uint32_t h2pack(float lo, float hi) {
    __half2 h = __floats2half2_rn(lo, hi);
    return *reinterpret_cast<uint32_t*>(&h);
}
__device__ __forceinline__ void mma_f16(float* c, const uint32_t* a, const uint32_t* b) {
    asm volatile(
        "mma.sync.aligned.m16n8k16.row.col.f32.f16.f16.f32 "
        "{%0,%1,%2,%3}, {%4,%5,%6,%7}, {%8,%9}, {%0,%1,%2,%3};"
        : "+f"(c[0]), "+f"(c[1]), "+f"(c[2]), "+f"(c[3])
        : "r"(a[0]), "r"(a[1]), "r"(a[2]), "r"(a[3]), "r"(b[0]), "r"(b[1]));
}
__device__ __forceinline__ void ldm_x4(uint32_t* r, uint32_t addr) {
    asm volatile("ldmatrix.sync.aligned.m8n8.x4.shared.b16 {%0,%1,%2,%3}, [%4];"
                 : "=r"(r[0]), "=r"(r[1]), "=r"(r[2]), "=r"(r[3]) : "r"(addr));
}

// ---------------- fp16 mma implicit-GEMM conv + BN + ReLU -------------------
// CTA tile 128(M) x 256(N), K-chunk 32 (two k16 steps). 8 warps = 2x4,
// warp tile 64x64. SMEM rows = 40 halfs (80 B): each ldmatrix 8-row phase
// hits all 32 banks once; each STS.128 quarter-warp likewise.
template<int CIN>
__global__ __launch_bounds__(256, 1)
void conv_mma(const float* __restrict__ in, const float* __restrict__ w,
              const float* __restrict__ cbias,
              const float* __restrict__ bng, const float* __restrict__ bnb,
              const float* __restrict__ bnm, const float* __restrict__ bnv,
              float* __restrict__ out)
{
    constexpr int K   = CIN * 9;
    constexpr int NKT = K / 32;
    constexpr uint32_t AOFF = 0;          // A: 128 rows x 80 B = 10240 B
    constexpr uint32_t BOFF = 10240;      // B: 256 rows x 80 B = 20480 B
    constexpr uint32_t BUFSZ = 30720;     // per double-buffer stage
    constexpr uint32_t TABOFF = 61440;

    extern __shared__ char smc[];
    const uint32_t sb = (uint32_t)__cvta_generic_to_shared(smc);

    const int t    = threadIdx.x;
    const int wid  = t >> 5;
    const int lane = t & 31;
    const int g    = lane >> 2;
    const int tig  = lane & 3;
    const int warp_m = (wid >> 2) * 64;
    const int warp_n = (wid & 3) * 64;

    const int m0    = blockIdx.x * 128;
    const int pix0  = blockIdx.y * 256;
    const int bn    = pix0 >> 12;
    const int lpix0 = pix0 & 4095;

    // im2col offset table: (elem_off+65) | (tap r << 21)
    int* tabp = (int*)(smc + TABOFF);
    for (int k = t; k < K; k += 256) {
        const int cin = k / 9;
        const int r   = k - cin * 9;
        const int dh  = r / 3 - 1;
        const int dw  = r - (r / 3) * 3 - 1;
        tabp[k] = ((cin * PIX + dh * HW + dw) + 65) | (r << 21);
    }
    __syncthreads();

    // B-gather: thread t owns pixel n = t (tile spans 4 image rows)
    const int hh = (lpix0 >> 6) + (t >> 6);
    const int ww = t & 63;
    const float* pTh = in + (size_t)bn * CIN * PIX + hh * HW + ww;
    unsigned msk = 0;
    #pragma unroll
    for (int r = 0; r < 9; r++) {
        const int dh = r / 3 - 1, dw = r % 3 - 1;
        if ((unsigned)(hh + dh) < (unsigned)HW && (unsigned)(ww + dw) < (unsigned)HW)
            msk |= 1u << r;
    }

    // A staging: thread owns weight row (t&127), k-half (t>>7)*16 floats
    const int ar = t & 127;
    const int ah = t >> 7;
    const float* wp = w + (size_t)(m0 + ar) * K + ah * 16;
    char* aDst0 = smc + AOFF + ar * 80 + ah * 32;
    char* bDst0 = smc + BOFF + t * 80;

    // ldmatrix per-lane base addresses
    const int rowA  = lane & 15;
    const int byteA = (lane >> 4) * 16;
    const int rowB  = (lane & 7) + ((lane >> 4) & 1) * 8;
    const int byteB = ((lane >> 3) & 1) * 16;
    const uint32_t aAddr = sb + AOFF + (uint32_t)(warp_m + rowA) * 80 + byteA;
    const uint32_t bAddr = sb + BOFF + (uint32_t)(warp_n + rowB) * 80 + byteB;

    uint32_t rAw[8];     // 16 halfs of A row, packed
    uint32_t rBw[16];    // 32 halfs of B, packed

    auto fetch = [&](int kt) {
        const int k0 = kt * 32;
        const float4 a0 = __ldg((const float4*)(wp + k0));
        const float4 a1 = __ldg((const float4*)(wp + k0 + 4));
        const float4 a2 = __ldg((const float4*)(wp + k0 + 8));
        const float4 a3 = __ldg((const float4*)(wp + k0 + 12));
        rAw[0] = h2pack(a0.x, a0.y); rAw[1] = h2pack(a0.z, a0.w);
        rAw[2] = h2pack(a1.x, a1.y); rAw[3] = h2pack(a1.z, a1.w);
        rAw[4] = h2pack(a2.x, a2.y); rAw[5] = h2pack(a2.z, a2.w);
        rAw[6] = h2pack(a3.x, a3.y); rAw[7] = h2pack(a3.z, a3.w);
        const int* tab = tabp + k0;
        #pragma unroll
        for (int j = 0; j < 16; j++) {
            const int e0 = tab[2 * j],     e1 = tab[2 * j + 1];
            const int r0 = e0 >> 21,       r1 = e1 >> 21;
            const int o0 = (e0 & 0x1FFFFF) - 65;
            const int o1 = (e1 & 0x1FFFFF) - 65;
            const float v0 = ((msk >> r0) & 1u) ? __ldg(pTh + o0) : 0.f;
            const float v1 = ((msk >> r1) & 1u) ? __ldg(pTh + o1) : 0.f;
            rBw[j] = h2pack(v0, v1);
        }
    };
    auto stage = [&](int buf) {
        char* aD = aDst0 + buf * BUFSZ;
        *(uint4*)(aD)      = make_uint4(rAw[0], rAw[1], rAw[2], rAw[3]);
        *(uint4*)(aD + 16) = make_uint4(rAw[4], rAw[5], rAw[6], rAw[7]);
        char* bD = bDst0 + buf * BUFSZ;
        *(uint4*)(bD)      = make_uint4(rBw[0],  rBw[1],  rBw[2],  rBw[3]);
        *(uint4*)(bD + 16) = make_uint4(rBw[4],  rBw[5],  rBw[6],  rBw[7]);
        *(uint4*)(bD + 32) = make_uint4(rBw[8],  rBw[9],  rBw[10], rBw[11]);
        *(uint4*)(bD + 48) = make_uint4(rBw[12], rBw[13], rBw[14], rBw[15]);
    };

    float c[4][8][4];
    #pragma unroll
    for (int mf = 0; mf < 4; mf++)
        #pragma unroll
        for (int nf = 0; nf < 8; nf++)
            #pragma unroll
            for (int i = 0; i < 4; i++) c[mf][nf][i] = 0.f;

    fetch(0);
    stage(0);
    __syncthreads();

    for (int kt = 0; kt < NKT; ++kt) {
        if (kt + 1 < NKT) fetch(kt + 1);

        const uint32_t bufo = (kt & 1) ? BUFSZ : 0;
        #pragma unroll
        for (int s = 0; s < 2; ++s) {
            uint32_t a[4][4];
            uint32_t b[8][2];
            #pragma unroll
            for (int mf = 0; mf < 4; mf++)
                ldm_x4(a[mf], aAddr + bufo + mf * 1280 + s * 32);
            #pragma unroll
            for (int p = 0; p < 4; p++) {
                uint32_t rr[4];
                ldm_x4(rr, bAddr + bufo + p * 1280 + s * 32);
                b[2 * p][0]     = rr[0];
                b[2 * p][1]     = rr[1];
                b[2 * p + 1][0] = rr[2];
                b[2 * p + 1][1] = rr[3];
            }
            #pragma unroll
            for (int mf = 0; mf < 4; mf++)
                #pragma unroll
                for (int nf = 0; nf < 8; nf++)
                    mma_f16(c[mf][nf], a[mf], b[nf]);
        }

        if (kt + 1 < NKT) stage((kt + 1) & 1);
        __syncthreads();
    }

    // ---- epilogue: BN + ReLU, direct to gmem (same as R7) -------------------
    #pragma unroll
    for (int mf = 0; mf < 4; mf++) {
        const int r0  = warp_m + mf * 16 + g;
        const int oc0 = m0 + r0;
        const int oc1 = oc0 + 8;
        const float s0  = bng[oc0] * rsqrtf(bnv[oc0] + 1e-5f);
        const float sh0 = (cbias[oc0] - bnm[oc0]) * s0 + bnb[oc0];
        const float s1  = bng[oc1] * rsqrtf(bnv[oc1] + 1e-5f);
        const float sh1 = (cbias[oc1] - bnm[oc1]) * s1 + bnb[oc1];
        float* o0 = out + ((size_t)(bn * HIDC + oc0)) * PIX + lpix0;
        float* o1 = o0 + 8 * PIX;
        #pragma unroll
        for (int nf = 0; nf < 8; nf++) {
            const int col = warp_n + nf * 8 + 2 * tig;
            float2 v0, v1;
            v0.x = fmaxf(fmaf(c[mf][nf][0], s0, sh0), 0.f);
            v0.y = fmaxf(fmaf(c[mf][nf][1], s0, sh0), 0.f);
            v1.x = fmaxf(fmaf(c[mf][nf][2], s1, sh1), 0.f);
            v1.y = fmaxf(fmaf(c[mf][nf][3], s1, sh1), 0.f);
            *(float2*)(o0 + col) = v0;
            *(float2*)(o1 + col) = v1;
        }
    }
}

// ---------------- adaptive avg pool 64x64 -> 4x4 ----------------------------
__global__ void pool_kernel(float* __restrict__ feat)
{
    const int nc = blockIdx.x;
    const int n  = nc >> 9;
    const int c  = nc & 511;
    const float* p = g_act2 + (size_t)nc * PIX;
    const int t = threadIdx.x;
    const int q = t >> 4, r = t & 15;
    const int qh = q >> 2, qw = q & 3;
    const float* row = p + (qh * 16 + r) * HW + qw * 16;
    float s = 0.f;
    #pragma unroll
    for (int j = 0; j < 16; j++) s += row[j];
    __shared__ float part[256];
    part[t] = s;
    __syncthreads();
    if (t < 16) {
        float acc = 0.f;
        #pragma unroll
        for (int j = 0; j < 16; j++) acc += part[t * 16 + j];
        feat[n * FLAT + c * 16 + t] = acc * (1.f / 256.f);
    }
}

// ---------------- clinical embedding (4 -> 128) -----------------------------
__global__ void clin_kernel(const float* __restrict__ x, const float* __restrict__ w,
                            const float* __restrict__ b, float* __restrict__ feat)
{
    const int n = blockIdx.x;
    const int j = threadIdx.x;
    float s = b[j];
    #pragma unroll
    for (int i = 0; i < 4; i++) s = fmaf(w[j * 4 + i], x[n * 4 + i], s);
    feat[n * FLAT + 8192 + j] = s;
}

// ---------------- generic linear: warp per (n, o) ---------------------------
__global__ void linear_kernel(const float* __restrict__ in, const float* __restrict__ w,
                              const float* __restrict__ b, float* __restrict__ out,
                              int In, int Out, int act)
{
    const int gw   = (blockIdx.x * blockDim.x + threadIdx.x) >> 5;
    const int lane = threadIdx.x & 31;
    if (gw >= 16 * Out) return;
    const int o = gw >> 4;
    const int n = gw & 15;
    const float* wr = w + (size_t)o * In;
    const float* xr = in + (size_t)n * In;
    float s = 0.f;
    for (int i = lane; i < In; i += 32) s = fmaf(wr[i], xr[i], s);
    #pragma unroll
    for (int off = 16; off; off >>= 1) s += __shfl_xor_sync(0xFFFFFFFFu, s, off);
    if (lane == 0) {
        s += b[o];
        if (act == 1)      s = fmaxf(s, 0.f);
        else if (act == 2) s = 1.f / (1.f + expf(-s));
        else if (act == 3) s = fminf(fmaxf(s, -5.f), 0.f);
        out[n * Out + o] = s;
    }
}

// ---------------- sampling head ---------------------------------------------
__global__ void head_kernel(const float* __restrict__ noise, const float* __restrict__ u,
                            float* __restrict__ out)
{
    const int t = threadIdx.x;
    if (t >= 48) return;
    const int n = t / 3, k = t % 3;
    const int nk = n * 3 + k;
    float pm[4], ls[4], p[4];
    float lp = 0.f;
    #pragma unroll
    for (int j = 0; j < 4; j++) {
        pm[j] = g_pm[n * 12 + k * 4 + j];
        ls[j] = g_ls[n * 12 + k * 4 + j];
        const float sd = expf(ls[j]);
        p[j] = pm[j] + noise[nk * 4 + j] * sd;
        const float z = (p[j] - pm[j]) / sd;
        lp += z * z + 2.f * ls[j];
    }
    lp *= -0.5f;
    #pragma unroll
    for (int j = 0; j < 4; j++) p[j] = fminf(fmaxf(p[j], 0.f), 1.f);
    const float cx = p[0], cy = p[1];
    const float s2 = p[2] * 0.2f + 0.1f;
    const float s3 = p[3] * 0.2f + 0.1f;
    out[480 + nk] = lp;
    out[528 + nk * 4 + 0] = cx;
    out[528 + nk * 4 + 1] = cy;
    out[528 + nk * 4 + 2] = s2;
    out[528 + nk * 4 + 3] = s3;
    #pragma unroll
    for (int pt = 0; pt < 5; pt++) {
        const float ux = u[(nk * 5 + pt) * 2 + 0];
        const float uy = u[(nk * 5 + pt) * 2 + 1];
        float px = (cx + (ux - 0.5f) * s2) * 256.f;
        float py = (cy + (uy - 0.5f) * s3) * 256.f;
        px = fminf(fmaxf(px, 0.f), 255.f);
        py = fminf(fmaxf(py, 0.f), 255.f);
        out[(n * 15 + k * 5 + pt) * 2 + 0] = px;
        out[(n * 15 + k * 5 + pt) * 2 + 1] = py;
    }
}

// ---------------- launcher ---------------------------------------------------
extern "C" void kernel_launch(void* const* d_in, const int* in_sizes, int n_in,
                              void* d_out, int out_size)
{
    const float* img   = (const float*)d_in[0];
    const float* clin  = (const float*)d_in[1];
    const float* noise = (const float*)d_in[2];
    const float* u     = (const float*)d_in[3];
    const float* c1w = (const float*)d_in[4];
    const float* c1b = (const float*)d_in[5];
    const float* b1g = (const float*)d_in[6];
    const float* b1b = (const float*)d_in[7];
    const float* b1m = (const float*)d_in[8];
    const float* b1v = (const float*)d_in[9];
    const float* c2w = (const float*)d_in[10];
    const float* c2b = (const float*)d_in[11];
    const float* b2g = (const float*)d_in[12];
    const float* b2b = (const float*)d_in[13];
    const float* b2m = (const float*)d_in[14];
    const float* b2v = (const float*)d_in[15];
    const float* clw = (const float*)d_in[16];
    const float* clb = (const float*)d_in[17];
    const float* p1w = (const float*)d_in[18];
    const float* p1b = (const float*)d_in[19];
    const float* p2w = (const float*)d_in[20];
    const float* p2b = (const float*)d_in[21];
    const float* p3w = (const float*)d_in[22];
    const float* p3b = (const float*)d_in[23];
    const float* l1w = (const float*)d_in[24];
    const float* l1b = (const float*)d_in[25];
    const float* l2w = (const float*)d_in[26];
    const float* l2b = (const float*)d_in[27];

    float *act1, *act2, *feat, *h1, *h2, *g1, *pm, *ls;
    cudaGetSymbolAddress((void**)&act1, g_act1);
    cudaGetSymbolAddress((void**)&act2, g_act2);
    cudaGetSymbolAddress((void**)&feat, g_feat);
    cudaGetSymbolAddress((void**)&h1,   g_h1);
    cudaGetSymbolAddress((void**)&h2,   g_h2);
    cudaGetSymbolAddress((void**)&g1,   g_g1);
    cudaGetSymbolAddress((void**)&pm,   g_pm);
    cudaGetSymbolAddress((void**)&ls,   g_ls);

    const int smem1 = 61440 + 2304 * 4;   // 70656
    const int smem2 = 61440 + 4608 * 4;   // 79872
    cudaFuncSetAttribute(conv_mma<256>, cudaFuncAttributeMaxDynamicSharedMemorySize, smem1);
    cudaFuncSetAttribute(conv_mma<512>, cudaFuncAttributeMaxDynamicSharedMemorySize, smem2);

    const dim3 cgrid(HIDC / 128, NPIX / 256);   // (4, 256)
    conv_mma<256><<<cgrid, 256, smem1>>>(img,  c1w, c1b, b1g, b1b, b1m, b1v, act1);
    conv_mma<512><<<cgrid, 256, smem2>>>(act1, c2w, c2b, b2g, b2b, b2m, b2v, act2);

    pool_kernel<<<BATCH * HIDC, 256>>>(feat);
    clin_kernel<<<BATCH, 128>>>(clin, clw, clb, feat);

    linear_kernel<<<(16 * 512 + 7) / 8, 256>>>(feat, p1w, p1b, h1, FLAT, 512, 1);
    linear_kernel<<<(16 * 256 + 7) / 8, 256>>>(h1,   p2w, p2b, h2, 512,  256, 1);
    linear_kernel<<<(16 * 12  + 7) / 8, 256>>>(h2,   p3w, p3b, pm, 256,  12,  2);
    linear_kernel<<<(16 * 256 + 7) / 8, 256>>>(feat, l1w, l1b, g1, FLAT, 256, 1);
    linear_kernel<<<(16 * 12  + 7) / 8, 256>>>(g1,   l2w, l2b, ls, 256,  12,  3);

    head_kernel<<<1, 64>>>(noise, u, (float*)d_out);
}

// round 12
// speedup vs baseline: 2.1681x; 2.1681x over previous
#include <cuda_runtime.h>
#include <cuda_fp16.h>
#include <cstdint>

// R12 = resubmit of R11 Winograd F(2x2,3x3) (container-level failure; code
// never executed; full math/bounds audit found no defect).
// Convs = input transform + 16 batched fp16 GEMMs (R10's measured-working
// mma/ldmatrix mainloop minus im2col) + output transform with fused BN+ReLU.
// 2.25x fewer MACs on a pipe measured FLOP-limited at ~256 MAC/cyc/SM.

#define BATCH 16
#define HIDC  512
#define HW    64
#define PIX   4096
#define NT    16384          /* total 4x4 tiles = 16 imgs * 32*32 */
#define FLAT  8320

// ---------------- scratch (static device globals) ---------------------------
__device__ __half g_U1[16 * 512 * 256];                  //  4 MiB
__device__ __half g_U2[16 * 512 * 512];                  //  8 MiB
__device__ __half g_V1[(size_t)16 * NT * 256];           // 128 MiB
__device__ __half g_V2[(size_t)16 * NT * 512];           // 256 MiB
__device__ __half g_M [(size_t)16 * 512 * NT];           // 256 MiB (reused)
__device__ __half g_act1h[(size_t)BATCH * HIDC * PIX];   //  64 MiB
__device__ float  g_act2 [(size_t)BATCH * HIDC * PIX];   // 128 MiB
__device__ float g_feat[BATCH * FLAT];
__device__ float g_h1[BATCH * 512];
__device__ float g_h2[BATCH * 256];
__device__ float g_g1[BATCH * 256];
__device__ float g_pm[BATCH * 12];
__device__ float g_ls[BATCH * 12];

// ---------------- helpers ----------------------------------------------------
__device__ __forceinline__ void mma_f16(float* c, const uint32_t* a, const uint32_t* b) {
    asm volatile(
        "mma.sync.aligned.m16n8k16.row.col.f32.f16.f16.f32 "
        "{%0,%1,%2,%3}, {%4,%5,%6,%7}, {%8,%9}, {%0,%1,%2,%3};"
        : "+f"(c[0]), "+f"(c[1]), "+f"(c[2]), "+f"(c[3])
        : "r"(a[0]), "r"(a[1]), "r"(a[2]), "r"(a[3]), "r"(b[0]), "r"(b[1]));
}
__device__ __forceinline__ void ldm_x4(uint32_t* r, uint32_t addr) {
    asm volatile("ldmatrix.sync.aligned.m8n8.x4.shared.b16 {%0,%1,%2,%3}, [%4];"
                 : "=r"(r[0]), "=r"(r[1]), "=r"(r[2]), "=r"(r[3]) : "r"(addr));
}

// ---------------- weight transform: U_e = G g G^T (fp32 -> fp16) -------------
template<int CIN>
__global__ void wt_kernel(const float* __restrict__ g, __half* __restrict__ U)
{
    const int idx = blockIdx.x * 256 + threadIdx.x;     // co*CIN + ci
    if (idx >= 512 * CIN) return;
    const int co = idx / CIN, ci = idx - co * CIN;
    const float* gp = g + (size_t)idx * 9;
    float w[3][3];
    #pragma unroll
    for (int a = 0; a < 3; a++)
        #pragma unroll
        for (int b = 0; b < 3; b++) w[a][b] = __ldg(gp + a * 3 + b);
    float t[4][3];
    #pragma unroll
    for (int b = 0; b < 3; b++) {
        t[0][b] = w[0][b];
        t[1][b] = 0.5f * (w[0][b] + w[1][b] + w[2][b]);
        t[2][b] = 0.5f * (w[0][b] - w[1][b] + w[2][b]);
        t[3][b] = w[2][b];
    }
    #pragma unroll
    for (int a = 0; a < 4; a++) {
        float u0 = t[a][0];
        float u1 = 0.5f * (t[a][0] + t[a][1] + t[a][2]);
        float u2 = 0.5f * (t[a][0] - t[a][1] + t[a][2]);
        float u3 = t[a][2];
        U[((size_t)(a * 4 + 0) * 512 + co) * CIN + ci] = __float2half_rn(u0);
        U[((size_t)(a * 4 + 1) * 512 + co) * CIN + ci] = __float2half_rn(u1);
        U[((size_t)(a * 4 + 2) * 512 + co) * CIN + ci] = __float2half_rn(u2);
        U[((size_t)(a * 4 + 3) * 512 + co) * CIN + ci] = __float2half_rn(u3);
    }
}

// ---------------- input transform: V_e[tau][ci] = (B^T d B)_e ----------------
// grid: (CIN/32, 512 = bn*32+ty), block 256.
// Phase 1: coalesced load of 32ci x 4rows x 64px patch into smem (fp32).
// Phase 2: warp lanes over ci -> 64B-coalesced V writes per (e, tau).
template<typename TI, int CIN>
__global__ __launch_bounds__(256)
void wino_in(const TI* __restrict__ in, __half* __restrict__ V)
{
    __shared__ float X[32 * 273];     // ci pitch 273 (odd): conflict-free reads
    const int t   = threadIdx.x;
    const int row = blockIdx.y;       // bn*32 + ty
    const int bn  = row >> 5, ty = row & 31;
    const int ci0 = blockIdx.x * 32;

    // phase 1: 32 iterations, k = ci_l; each thread loads one element
    {
        const int a = t >> 6, w = t & 63;
        const int hh = 2 * ty - 1 + a;
        const bool hok = (unsigned)hh < (unsigned)HW;
        for (int k = 0; k < 32; k++) {
            float v = 0.f;
            if (hok)
                v = (float)__ldg(in + ((size_t)(bn * CIN + ci0 + k)) * PIX + hh * HW + w);
            X[k * 273 + a * 66 + w] = v;
        }
    }
    __syncthreads();

    // phase 2: thread = (ci_l = t&31, tx in {t>>5 + 8k})
    const int ci_l = t & 31;
    const int txg  = t >> 5;
    const float* Xr = X + ci_l * 273;
    #pragma unroll
    for (int txk = 0; txk < 4; txk++) {
        const int tx = txg + 8 * txk;
        const int w0 = 2 * tx - 1;
        float d[4][4];
        #pragma unroll
        for (int a = 0; a < 4; a++)
            #pragma unroll
            for (int b = 0; b < 4; b++) {
                const int ww = w0 + b;
                d[a][b] = ((unsigned)ww < (unsigned)HW) ? Xr[a * 66 + ww] : 0.f;
            }
        float tt[4][4];
        #pragma unroll
        for (int b = 0; b < 4; b++) {
            tt[0][b] = d[0][b] - d[2][b];
            tt[1][b] = d[1][b] + d[2][b];
            tt[2][b] = d[2][b] - d[1][b];
            tt[3][b] = d[1][b] - d[3][b];
        }
        const size_t tau = (size_t)row * 32 + tx;
        __half* vp = V + tau * CIN + ci0 + ci_l;
        const size_t estr = (size_t)NT * CIN;
        #pragma unroll
        for (int a = 0; a < 4; a++) {
            const float v0 = tt[a][0] - tt[a][2];
            const float v1 = tt[a][1] + tt[a][2];
            const float v2 = tt[a][2] - tt[a][1];
            const float v3 = tt[a][1] - tt[a][3];
            vp[(size_t)(a * 4 + 0) * estr] = __float2half_rn(v0);
            vp[(size_t)(a * 4 + 1) * estr] = __float2half_rn(v1);
            vp[(size_t)(a * 4 + 2) * estr] = __float2half_rn(v2);
            vp[(size_t)(a * 4 + 3) * estr] = __float2half_rn(v3);
        }
    }
}

// ---------------- batched fp16 GEMM: M_e[co][tau] = U_e x V_e^T --------------
// grid (4 co-blocks, 64 tau-blocks, 16 e). CTA 128co x 256tau, K = CIN.
// Mainloop identical to R10 (ldmatrix.x4 + mma.16816, 80B smem rows).
template<int CIN>
__global__ __launch_bounds__(256, 1)
void wgemm(const __half* __restrict__ U, const __half* __restrict__ V,
           __half* __restrict__ M)
{
    constexpr int NKT = CIN / 32;
    constexpr uint32_t AOFF = 0;          // A: 128 x 80B
    constexpr uint32_t BOFF = 10240;      // B: 256 x 80B
    constexpr uint32_t BUFSZ = 30720;

    extern __shared__ char smc[];
    const uint32_t sb = (uint32_t)__cvta_generic_to_shared(smc);

    const int t    = threadIdx.x;
    const int wid  = t >> 5;
    const int lane = t & 31;
    const int g    = lane >> 2;
    const int tig  = lane & 3;
    const int warp_m = (wid >> 2) * 64;
    const int warp_n = (wid & 3) * 64;

    const int m0   = blockIdx.x * 128;
    const int tau0 = blockIdx.y * 256;
    const int e    = blockIdx.z;

    const __half* Ae = U + ((size_t)e * 512 + m0) * CIN;
    const __half* Be = V + ((size_t)e * NT + tau0) * CIN;

    const int ar = t & 127, ah = t >> 7;
    const __half* wp = Ae + (size_t)ar * CIN + ah * 16;
    const __half* bp = Be + (size_t)t * CIN;
    char* aDst0 = smc + AOFF + ar * 80 + ah * 32;
    char* bDst0 = smc + BOFF + t * 80;

    const int rowA  = lane & 15;
    const int byteA = (lane >> 4) * 16;
    const int rowB  = (lane & 7) + ((lane >> 4) & 1) * 8;
    const int byteB = ((lane >> 3) & 1) * 16;
    const uint32_t aAddr = sb + AOFF + (uint32_t)(warp_m + rowA) * 80 + byteA;
    const uint32_t bAddr = sb + BOFF + (uint32_t)(warp_n + rowB) * 80 + byteB;

    uint4 ra0, ra1, rb0, rb1, rb2, rb3;

    auto fetch = [&](int kt) {
        const int k0 = kt * 32;
        ra0 = __ldg((const uint4*)(wp + k0));
        ra1 = __ldg((const uint4*)(wp + k0 + 8));
        rb0 = __ldg((const uint4*)(bp + k0));
        rb1 = __ldg((const uint4*)(bp + k0 + 8));
        rb2 = __ldg((const uint4*)(bp + k0 + 16));
        rb3 = __ldg((const uint4*)(bp + k0 + 24));
    };
    auto stage = [&](int buf) {
        char* aD = aDst0 + buf * BUFSZ;
        *(uint4*)(aD)      = ra0;
        *(uint4*)(aD + 16) = ra1;
        char* bD = bDst0 + buf * BUFSZ;
        *(uint4*)(bD)      = rb0;
        *(uint4*)(bD + 16) = rb1;
        *(uint4*)(bD + 32) = rb2;
        *(uint4*)(bD + 48) = rb3;
    };

    float c[4][8][4];
    #pragma unroll
    for (int mf = 0; mf < 4; mf++)
        #pragma unroll
        for (int nf = 0; nf < 8; nf++)
            #pragma unroll
            for (int i = 0; i < 4; i++) c[mf][nf][i] = 0.f;

    fetch(0);
    stage(0);
    __syncthreads();

    for (int kt = 0; kt < NKT; ++kt) {
        if (kt + 1 < NKT) fetch(kt + 1);

        const uint32_t bufo = (kt & 1) ? BUFSZ : 0;
        #pragma unroll
        for (int s = 0; s < 2; ++s) {
            uint32_t a[4][4];
            uint32_t b[8][2];
            #pragma unroll
            for (int mf = 0; mf < 4; mf++)
                ldm_x4(a[mf], aAddr + bufo + mf * 1280 + s * 32);
            #pragma unroll
            for (int p = 0; p < 4; p++) {
                uint32_t rr[4];
                ldm_x4(rr, bAddr + bufo + p * 1280 + s * 32);
                b[2 * p][0]     = rr[0];
                b[2 * p][1]     = rr[1];
                b[2 * p + 1][0] = rr[2];
                b[2 * p + 1][1] = rr[3];
            }
            #pragma unroll
            for (int mf = 0; mf < 4; mf++)
                #pragma unroll
                for (int nf = 0; nf < 8; nf++)
                    mma_f16(c[mf][nf], a[mf], b[nf]);
        }

        if (kt + 1 < NKT) stage((kt + 1) & 1);
        __syncthreads();
    }

    // epilogue: write M_e[co][tau] fp16
    #pragma unroll
    for (int mf = 0; mf < 4; mf++) {
        const int co0 = m0 + warp_m + mf * 16 + g;
        __half* o0 = M + ((size_t)e * 512 + co0) * NT + tau0;
        __half* o1 = o0 + (size_t)8 * NT;
        #pragma unroll
        for (int nf = 0; nf < 8; nf++) {
            const int col = warp_n + nf * 8 + 2 * tig;
            *(__half2*)(o0 + col) = __floats2half2_rn(c[mf][nf][0], c[mf][nf][1]);
            *(__half2*)(o1 + col) = __floats2half2_rn(c[mf][nf][2], c[mf][nf][3]);
        }
    }
}

// ---------------- output transform: A^T M A + BN + ReLU ----------------------
// thread per (co, tau); warp = 32 consecutive tau -> coalesced M reads/out writes.
template<bool OUTH>
__global__ void wout(const __half* __restrict__ M,
                     const float* __restrict__ cbias,
                     const float* __restrict__ bng, const float* __restrict__ bnb,
                     const float* __restrict__ bnm, const float* __restrict__ bnv,
                     void* __restrict__ outv)
{
    const int gid = blockIdx.x * 256 + threadIdx.x;
    const int tau = gid & (NT - 1);
    const int co  = gid >> 14;

    float m[16];
    const __half* mp = M + (size_t)co * NT + tau;
    #pragma unroll
    for (int e = 0; e < 16; e++)
        m[e] = (float)__ldg(mp + (size_t)e * 512 * NT);

    float s0[4], s1[4];
    #pragma unroll
    for (int b = 0; b < 4; b++) {
        s0[b] = m[b] + m[4 + b] + m[8 + b];
        s1[b] = m[4 + b] - m[8 + b] - m[12 + b];
    }
    const float o00 = s0[0] + s0[1] + s0[2];
    const float o01 = s0[1] - s0[2] - s0[3];
    const float o10 = s1[0] + s1[1] + s1[2];
    const float o11 = s1[1] - s1[2] - s1[3];

    const float sc = bng[co] * rsqrtf(bnv[co] + 1e-5f);
    const float sh = (cbias[co] - bnm[co]) * sc + bnb[co];
    const float v00 = fmaxf(fmaf(o00, sc, sh), 0.f);
    const float v01 = fmaxf(fmaf(o01, sc, sh), 0.f);
    const float v10 = fmaxf(fmaf(o10, sc, sh), 0.f);
    const float v11 = fmaxf(fmaf(o11, sc, sh), 0.f);

    const int bn = tau >> 10;
    const int ty = (tau & 1023) >> 5;
    const int tx = tau & 31;
    const size_t base = ((size_t)(bn * HIDC + co)) * PIX + (2 * ty) * HW + 2 * tx;
    if (OUTH) {
        __half* o = (__half*)outv;
        *(__half2*)(o + base)      = __floats2half2_rn(v00, v01);
        *(__half2*)(o + base + HW) = __floats2half2_rn(v10, v11);
    } else {
        float* o = (float*)outv;
        *(float2*)(o + base)      = make_float2(v00, v01);
        *(float2*)(o + base + HW) = make_float2(v10, v11);
    }
}

// ---------------- adaptive avg pool 64x64 -> 4x4 ----------------------------
__global__ void pool_kernel(float* __restrict__ feat)
{
    const int nc = blockIdx.x;
    const int n  = nc >> 9;
    const int c  = nc & 511;
    const float* p = g_act2 + (size_t)nc * PIX;
    const int t = threadIdx.x;
    const int q = t >> 4, r = t & 15;
    const int qh = q >> 2, qw = q & 3;
    const float* row = p + (qh * 16 + r) * HW + qw * 16;
    float s = 0.f;
    #pragma unroll
    for (int j = 0; j < 16; j++) s += row[j];
    __shared__ float part[256];
    part[t] = s;
    __syncthreads();
    if (t < 16) {
        float acc = 0.f;
        #pragma unroll
        for (int j = 0; j < 16; j++) acc += part[t * 16 + j];
        feat[n * FLAT + c * 16 + t] = acc * (1.f / 256.f);
    }
}

// ---------------- clinical embedding (4 -> 128) -----------------------------
__global__ void clin_kernel(const float* __restrict__ x, const float* __restrict__ w,
                            const float* __restrict__ b, float* __restrict__ feat)
{
    const int n = blockIdx.x;
    const int j = threadIdx.x;
    float s = b[j];
    #pragma unroll
    for (int i = 0; i < 4; i++) s = fmaf(w[j * 4 + i], x[n * 4 + i], s);
    feat[n * FLAT + 8192 + j] = s;
}

// ---------------- generic linear: warp per (n, o) ---------------------------
__global__ void linear_kernel(const float* __restrict__ in, const float* __restrict__ w,
                              const float* __restrict__ b, float* __restrict__ out,
                              int In, int Out, int act)
{
    const int gw   = (blockIdx.x * blockDim.x + threadIdx.x) >> 5;
    const int lane = threadIdx.x & 31;
    if (gw >= 16 * Out) return;
    const int o = gw >> 4;
    const int n = gw & 15;
    const float* wr = w + (size_t)o * In;
    const float* xr = in + (size_t)n * In;
    float s = 0.f;
    for (int i = lane; i < In; i += 32) s = fmaf(wr[i], xr[i], s);
    #pragma unroll
    for (int off = 16; off; off >>= 1) s += __shfl_xor_sync(0xFFFFFFFFu, s, off);
    if (lane == 0) {
        s += b[o];
        if (act == 1)      s = fmaxf(s, 0.f);
        else if (act == 2) s = 1.f / (1.f + expf(-s));
        else if (act == 3) s = fminf(fmaxf(s, -5.f), 0.f);
        out[n * Out + o] = s;
    }
}

// ---------------- sampling head ---------------------------------------------
__global__ void head_kernel(const float* __restrict__ noise, const float* __restrict__ u,
                            float* __restrict__ out)
{
    const int t = threadIdx.x;
    if (t >= 48) return;
    const int n = t / 3, k = t % 3;
    const int nk = n * 3 + k;
    float pm[4], ls[4], p[4];
    float lp = 0.f;
    #pragma unroll
    for (int j = 0; j < 4; j++) {
        pm[j] = g_pm[n * 12 + k * 4 + j];
        ls[j] = g_ls[n * 12 + k * 4 + j];
        const float sd = expf(ls[j]);
        p[j] = pm[j] + noise[nk * 4 + j] * sd;
        const float z = (p[j] - pm[j]) / sd;
        lp += z * z + 2.f * ls[j];
    }
    lp *= -0.5f;
    #pragma unroll
    for (int j = 0; j < 4; j++) p[j] = fminf(fmaxf(p[j], 0.f), 1.f);
    const float cx = p[0], cy = p[1];
    const float s2 = p[2] * 0.2f + 0.1f;
    const float s3 = p[3] * 0.2f + 0.1f;
    out[480 + nk] = lp;
    out[528 + nk * 4 + 0] = cx;
    out[528 + nk * 4 + 1] = cy;
    out[528 + nk * 4 + 2] = s2;
    out[528 + nk * 4 + 3] = s3;
    #pragma unroll
    for (int pt = 0; pt < 5; pt++) {
        const float ux = u[(nk * 5 + pt) * 2 + 0];
        const float uy = u[(nk * 5 + pt) * 2 + 1];
        float px = (cx + (ux - 0.5f) * s2) * 256.f;
        float py = (cy + (uy - 0.5f) * s3) * 256.f;
        px = fminf(fmaxf(px, 0.f), 255.f);
        py = fminf(fmaxf(py, 0.f), 255.f);
        out[(n * 15 + k * 5 + pt) * 2 + 0] = px;
        out[(n * 15 + k * 5 + pt) * 2 + 1] = py;
    }
}

// ---------------- launcher ---------------------------------------------------
extern "C" void kernel_launch(void* const* d_in, const int* in_sizes, int n_in,
                              void* d_out, int out_size)
{
    const float* img   = (const float*)d_in[0];
    const float* clin  = (const float*)d_in[1];
    const float* noise = (const float*)d_in[2];
    const float* u     = (const float*)d_in[3];
    const float* c1w = (const float*)d_in[4];
    const float* c1b = (const float*)d_in[5];
    const float* b1g = (const float*)d_in[6];
    const float* b1b = (const float*)d_in[7];
    const float* b1m = (const float*)d_in[8];
    const float* b1v = (const float*)d_in[9];
    const float* c2w = (const float*)d_in[10];
    const float* c2b = (const float*)d_in[11];
    const float* b2g = (const float*)d_in[12];
    const float* b2b = (const float*)d_in[13];
    const float* b2m = (const float*)d_in[14];
    const float* b2v = (const float*)d_in[15];
    const float* clw = (const float*)d_in[16];
    const float* clb = (const float*)d_in[17];
    const float* p1w = (const float*)d_in[18];
    const float* p1b = (const float*)d_in[19];
    const float* p2w = (const float*)d_in[20];
    const float* p2b = (const float*)d_in[21];
    const float* p3w = (const float*)d_in[22];
    const float* p3b = (const float*)d_in[23];
    const float* l1w = (const float*)d_in[24];
    const float* l1b = (const float*)d_in[25];
    const float* l2w = (const float*)d_in[26];
    const float* l2b = (const float*)d_in[27];

    __half *U1, *U2, *V1, *V2, *Mm, *act1h;
    float *act2, *feat, *h1, *h2, *g1, *pm, *ls;
    cudaGetSymbolAddress((void**)&U1,    g_U1);
    cudaGetSymbolAddress((void**)&U2,    g_U2);
    cudaGetSymbolAddress((void**)&V1,    g_V1);
    cudaGetSymbolAddress((void**)&V2,    g_V2);
    cudaGetSymbolAddress((void**)&Mm,    g_M);
    cudaGetSymbolAddress((void**)&act1h, g_act1h);
    cudaGetSymbolAddress((void**)&act2,  g_act2);
    cudaGetSymbolAddress((void**)&feat,  g_feat);
    cudaGetSymbolAddress((void**)&h1,    g_h1);
    cudaGetSymbolAddress((void**)&h2,    g_h2);
    cudaGetSymbolAddress((void**)&g1,    g_g1);
    cudaGetSymbolAddress((void**)&pm,    g_pm);
    cudaGetSymbolAddress((void**)&ls,    g_ls);

    const int gsmem = 61440;
    cudaFuncSetAttribute(wgemm<256>, cudaFuncAttributeMaxDynamicSharedMemorySize, gsmem);
    cudaFuncSetAttribute(wgemm<512>, cudaFuncAttributeMaxDynamicSharedMemorySize, gsmem);

    // ---- conv1 (Winograd) ----
    wt_kernel<256><<<512, 256>>>(c1w, U1);
    wino_in<float, 256><<<dim3(8, 512), 256>>>(img, V1);
    wgemm<256><<<dim3(4, 64, 16), 256, gsmem>>>(U1, V1, Mm);
    wout<true><<<32768, 256>>>(Mm, c1b, b1g, b1b, b1m, b1v, act1h);

    // ---- conv2 (Winograd) ----
    wt_kernel<512><<<1024, 256>>>(c2w, U2);
    wino_in<__half, 512><<<dim3(16, 512), 256>>>(act1h, V2);
    wgemm<512><<<dim3(4, 64, 16), 256, gsmem>>>(U2, V2, Mm);
    wout<false><<<32768, 256>>>(Mm, c2b, b2g, b2b, b2m, b2v, act2);

    // ---- tail ----
    pool_kernel<<<BATCH * HIDC, 256>>>(feat);
    clin_kernel<<<BATCH, 128>>>(clin, clw, clb, feat);

    linear_kernel<<<(16 * 512 + 7) / 8, 256>>>(feat, p1w, p1b, h1, FLAT, 512, 1);
    linear_kernel<<<(16 * 256 + 7) / 8, 256>>>(h1,   p2w, p2b, h2, 512,  256, 1);
    linear_kernel<<<(16 * 12  + 7) / 8, 256>>>(h2,   p3w, p3b, pm, 256,  12,  2);
    linear_kernel<<<(16 * 256 + 7) / 8, 256>>>(feat, l1w, l1b, g1, FLAT, 256, 1);
    linear_kernel<<<(16 * 12  + 7) / 8, 256>>>(g1,   l2w, l2b, ls, 256,  12,  3);

    head_kernel<<<1, 64>>>(noise, u, (float*)d_out);
}

// round 13
// speedup vs baseline: 3.2733x; 1.5097x over previous
#include <cuda_runtime.h>
#include <cuda_fp16.h>
#include <cstdint>

// R13: Winograd F(4x4,3x3) — 36 batched fp16 GEMMs (M=512, N=4096, K=CIN),
// fp32 M for numerical safety, fused BN+ReLU in output transform.
// 1.78x fewer MACs than R12's F(2x2) on a pipe FLOP-limited at 256 MAC/cyc/SM.

#define BATCH 16
#define HIDC  512
#define HW    64
#define PIX   4096
#define NT    4096           /* 4x4-output tiles: 16 imgs * 16*16 */
#define FLAT  8320

// ---------------- scratch (static device globals) ---------------------------
__device__ __half g_U1[36 * 512 * 256];                  //   9 MiB
__device__ __half g_U2[36 * 512 * 512];                  //  18 MiB
__device__ __half g_V1[(size_t)36 * NT * 256];           //  72 MiB
__device__ __half g_V2[(size_t)36 * NT * 512];           // 144 MiB
__device__ float  g_M [(size_t)36 * 512 * NT];           // 288 MiB (reused)
__device__ __half g_act1h[(size_t)BATCH * HIDC * PIX];   //  64 MiB
__device__ float  g_act2 [(size_t)BATCH * HIDC * PIX];   // 128 MiB
__device__ float g_feat[BATCH * FLAT];
__device__ float g_h1[BATCH * 512];
__device__ float g_h2[BATCH * 256];
__device__ float g_g1[BATCH * 256];
__device__ float g_pm[BATCH * 12];
__device__ float g_ls[BATCH * 12];

// ---------------- helpers ----------------------------------------------------
__device__ __forceinline__ void mma_f16(float* c, const uint32_t* a, const uint32_t* b) {
    asm volatile(
        "mma.sync.aligned.m16n8k16.row.col.f32.f16.f16.f32 "
        "{%0,%1,%2,%3}, {%4,%5,%6,%7}, {%8,%9}, {%0,%1,%2,%3};"
        : "+f"(c[0]), "+f"(c[1]), "+f"(c[2]), "+f"(c[3])
        : "r"(a[0]), "r"(a[1]), "r"(a[2]), "r"(a[3]), "r"(b[0]), "r"(b[1]));
}
__device__ __forceinline__ void ldm_x4(uint32_t* r, uint32_t addr) {
    asm volatile("ldmatrix.sync.aligned.m8n8.x4.shared.b16 {%0,%1,%2,%3}, [%4];"
                 : "=r"(r[0]), "=r"(r[1]), "=r"(r[2]), "=r"(r[3]) : "r"(addr));
}

// ---------------- weight transform: U_e = G g G^T (F(4,3)) -------------------
template<int CIN>
__global__ void wt43(const float* __restrict__ g, __half* __restrict__ U)
{
    const int idx = blockIdx.x * 256 + threadIdx.x;     // co*CIN + ci
    if (idx >= 512 * CIN) return;
    const int co = idx / CIN, ci = idx - co * CIN;
    const float* gp = g + (size_t)idx * 9;
    float w[3][3];
    #pragma unroll
    for (int a = 0; a < 3; a++)
        #pragma unroll
        for (int b = 0; b < 3; b++) w[a][b] = __ldg(gp + a * 3 + b);

    const float c6 = 1.f / 6.f, c12 = 1.f / 12.f, c24 = 1.f / 24.f;
    float t[6][3];
    #pragma unroll
    for (int b = 0; b < 3; b++) {
        t[0][b] = 0.25f * w[0][b];
        t[1][b] = -(w[0][b] + w[1][b] + w[2][b]) * c6;
        t[2][b] = (-w[0][b] + w[1][b] - w[2][b]) * c6;
        t[3][b] = w[0][b] * c24 + w[1][b] * c12 + w[2][b] * c6;
        t[4][b] = w[0][b] * c24 - w[1][b] * c12 + w[2][b] * c6;
        t[5][b] = w[2][b];
    }
    #pragma unroll
    for (int i = 0; i < 6; i++) {
        float u[6];
        u[0] = 0.25f * t[i][0];
        u[1] = -(t[i][0] + t[i][1] + t[i][2]) * c6;
        u[2] = (-t[i][0] + t[i][1] - t[i][2]) * c6;
        u[3] = t[i][0] * c24 + t[i][1] * c12 + t[i][2] * c6;
        u[4] = t[i][0] * c24 - t[i][1] * c12 + t[i][2] * c6;
        u[5] = t[i][2];
        #pragma unroll
        for (int j = 0; j < 6; j++)
            U[((size_t)(i * 6 + j) * 512 + co) * CIN + ci] = __float2half_rn(u[j]);
    }
}

// ---------------- input transform: V_e[tau][ci] = (B^T d B)_e ----------------
// grid (CIN/32, 256 = bn*16+ty), block 256. 6-row x 64-col patch (stride-4
// tiles). Smem fp16, per-ci pitch 386 halfs (772B -> conflict-free lanes).
template<typename TI, int CIN>
__global__ __launch_bounds__(256)
void wino_in43(const TI* __restrict__ in, __half* __restrict__ V)
{
    __shared__ __half X[32 * 386];
    const int t   = threadIdx.x;
    const int row = blockIdx.y;       // bn*16 + ty
    const int bn  = row >> 4, ty = row & 15;
    const int ci0 = blockIdx.x * 32;

    // phase 1: positions (a 0..5, w 0..63); loop k over 32 ci (coalesced in w)
    #pragma unroll
    for (int it = 0; it < 2; it++) {
        const int pos = t + it * 256;
        if (pos < 384) {
            const int a = pos >> 6, w = pos & 63;
            const int hh = 4 * ty - 1 + a;
            const bool hok = (unsigned)hh < (unsigned)HW;
            for (int k = 0; k < 32; k++) {
                __half v = __float2half_rn(0.f);
                if (hok)
                    v = (__half)(in[((size_t)(bn * CIN + ci0 + k)) * PIX + hh * HW + w]);
                X[k * 386 + a * 64 + w] = v;
            }
        }
    }
    __syncthreads();

    // phase 2: (ci_l = t&31, tx = (t>>5) + 8*txk)
    const int ci_l = t & 31;
    const int txg  = t >> 5;
    const __half* Xr = X + ci_l * 386;
    #pragma unroll
    for (int txk = 0; txk < 2; txk++) {
        const int tx = txg + 8 * txk;
        const int w0 = 4 * tx - 1;
        float d[6][6];
        #pragma unroll
        for (int a = 0; a < 6; a++)
            #pragma unroll
            for (int b = 0; b < 6; b++) {
                const int ww = w0 + b;
                d[a][b] = ((unsigned)ww < (unsigned)HW) ? (float)Xr[a * 64 + ww] : 0.f;
            }
        // rows: tB = B^T d
        float tb[6][6];
        #pragma unroll
        for (int b = 0; b < 6; b++) {
            tb[0][b] = 4.f * d[0][b] - 5.f * d[2][b] + d[4][b];
            tb[1][b] = -4.f * d[1][b] - 4.f * d[2][b] + d[3][b] + d[4][b];
            tb[2][b] = 4.f * d[1][b] - 4.f * d[2][b] - d[3][b] + d[4][b];
            tb[3][b] = -2.f * d[1][b] - d[2][b] + 2.f * d[3][b] + d[4][b];
            tb[4][b] = 2.f * d[1][b] - d[2][b] - 2.f * d[3][b] + d[4][b];
            tb[5][b] = 4.f * d[1][b] - 5.f * d[3][b] + d[5][b];
        }
        const size_t tau = (size_t)row * 16 + tx;
        __half* vp = V + tau * CIN + ci0 + ci_l;
        const size_t estr = (size_t)NT * CIN;
        #pragma unroll
        for (int i = 0; i < 6; i++) {
            float v[6];
            v[0] = 4.f * tb[i][0] - 5.f * tb[i][2] + tb[i][4];
            v[1] = -4.f * tb[i][1] - 4.f * tb[i][2] + tb[i][3] + tb[i][4];
            v[2] = 4.f * tb[i][1] - 4.f * tb[i][2] - tb[i][3] + tb[i][4];
            v[3] = -2.f * tb[i][1] - tb[i][2] + 2.f * tb[i][3] + tb[i][4];
            v[4] = 2.f * tb[i][1] - tb[i][2] - 2.f * tb[i][3] + tb[i][4];
            v[5] = 4.f * tb[i][1] - 5.f * tb[i][3] + tb[i][5];
            #pragma unroll
            for (int j = 0; j < 6; j++)
                vp[(size_t)(i * 6 + j) * estr] = __float2half_rn(v[j]);
        }
    }
}

// ---------------- batched fp16 GEMM: M_e[co][tau] = U_e x V_e^T (fp32 out) ---
// grid (4, 16, 36). CTA 128co x 256tau, K = CIN. R10's measured mainloop.
template<int CIN>
__global__ __launch_bounds__(256, 1)
void wgemm(const __half* __restrict__ U, const __half* __restrict__ V,
           float* __restrict__ M)
{
    constexpr int NKT = CIN / 32;
    constexpr uint32_t AOFF = 0;
    constexpr uint32_t BOFF = 10240;
    constexpr uint32_t BUFSZ = 30720;

    extern __shared__ char smc[];
    const uint32_t sb = (uint32_t)__cvta_generic_to_shared(smc);

    const int t    = threadIdx.x;
    const int wid  = t >> 5;
    const int lane = t & 31;
    const int g    = lane >> 2;
    const int tig  = lane & 3;
    const int warp_m = (wid >> 2) * 64;
    const int warp_n = (wid & 3) * 64;

    const int m0   = blockIdx.x * 128;
    const int tau0 = blockIdx.y * 256;
    const int e    = blockIdx.z;

    const __half* Ae = U + ((size_t)e * 512 + m0) * CIN;
    const __half* Be = V + ((size_t)e * NT + tau0) * CIN;

    const int ar = t & 127, ah = t >> 7;
    const __half* wp = Ae + (size_t)ar * CIN + ah * 16;
    const __half* bp = Be + (size_t)t * CIN;
    char* aDst0 = smc + AOFF + ar * 80 + ah * 32;
    char* bDst0 = smc + BOFF + t * 80;

    const int rowA  = lane & 15;
    const int byteA = (lane >> 4) * 16;
    const int rowB  = (lane & 7) + ((lane >> 4) & 1) * 8;
    const int byteB = ((lane >> 3) & 1) * 16;
    const uint32_t aAddr = sb + AOFF + (uint32_t)(warp_m + rowA) * 80 + byteA;
    const uint32_t bAddr = sb + BOFF + (uint32_t)(warp_n + rowB) * 80 + byteB;

    uint4 ra0, ra1, rb0, rb1, rb2, rb3;

    auto fetch = [&](int kt) {
        const int k0 = kt * 32;
        ra0 = __ldg((const uint4*)(wp + k0));
        ra1 = __ldg((const uint4*)(wp + k0 + 8));
        rb0 = __ldg((const uint4*)(bp + k0));
        rb1 = __ldg((const uint4*)(bp + k0 + 8));
        rb2 = __ldg((const uint4*)(bp + k0 + 16));
        rb3 = __ldg((const uint4*)(bp + k0 + 24));
    };
    auto stage = [&](int buf) {
        char* aD = aDst0 + buf * BUFSZ;
        *(uint4*)(aD)      = ra0;
        *(uint4*)(aD + 16) = ra1;
        char* bD = bDst0 + buf * BUFSZ;
        *(uint4*)(bD)      = rb0;
        *(uint4*)(bD + 16) = rb1;
        *(uint4*)(bD + 32) = rb2;
        *(uint4*)(bD + 48) = rb3;
    };

    float c[4][8][4];
    #pragma unroll
    for (int mf = 0; mf < 4; mf++)
        #pragma unroll
        for (int nf = 0; nf < 8; nf++)
            #pragma unroll
            for (int i = 0; i < 4; i++) c[mf][nf][i] = 0.f;

    fetch(0);
    stage(0);
    __syncthreads();

    for (int kt = 0; kt < NKT; ++kt) {
        if (kt + 1 < NKT) fetch(kt + 1);

        const uint32_t bufo = (kt & 1) ? BUFSZ : 0;
        #pragma unroll
        for (int s = 0; s < 2; ++s) {
            uint32_t a[4][4];
            uint32_t b[8][2];
            #pragma unroll
            for (int mf = 0; mf < 4; mf++)
                ldm_x4(a[mf], aAddr + bufo + mf * 1280 + s * 32);
            #pragma unroll
            for (int p = 0; p < 4; p++) {
                uint32_t rr[4];
                ldm_x4(rr, bAddr + bufo + p * 1280 + s * 32);
                b[2 * p][0]     = rr[0];
                b[2 * p][1]     = rr[1];
                b[2 * p + 1][0] = rr[2];
                b[2 * p + 1][1] = rr[3];
            }
            #pragma unroll
            for (int mf = 0; mf < 4; mf++)
                #pragma unroll
                for (int nf = 0; nf < 8; nf++)
                    mma_f16(c[mf][nf], a[mf], b[nf]);
        }

        if (kt + 1 < NKT) stage((kt + 1) & 1);
        __syncthreads();
    }

    // epilogue: write M_e[co][tau] fp32
    #pragma unroll
    for (int mf = 0; mf < 4; mf++) {
        const int co0 = m0 + warp_m + mf * 16 + g;
        float* o0 = M + ((size_t)e * 512 + co0) * NT + tau0;
        float* o1 = o0 + (size_t)8 * NT;
        #pragma unroll
        for (int nf = 0; nf < 8; nf++) {
            const int col = warp_n + nf * 8 + 2 * tig;
            *(float2*)(o0 + col) = make_float2(c[mf][nf][0], c[mf][nf][1]);
            *(float2*)(o1 + col) = make_float2(c[mf][nf][2], c[mf][nf][3]);
        }
    }
}

// ---------------- output transform: A^T M A + BN + ReLU ----------------------
// thread per (co, tau); lanes = consecutive tau -> coalesced M reads.
template<bool OUTH>
__global__ void wout43(const float* __restrict__ M,
                       const float* __restrict__ cbias,
                       const float* __restrict__ bng, const float* __restrict__ bnb,
                       const float* __restrict__ bnm, const float* __restrict__ bnv,
                       void* __restrict__ outv)
{
    const int gid = blockIdx.x * 256 + threadIdx.x;   // 512*4096
    const int tau = gid & (NT - 1);
    const int co  = gid >> 12;

    float m[36];
    const float* mp = M + (size_t)co * NT + tau;
    #pragma unroll
    for (int e = 0; e < 36; e++)
        m[e] = __ldg(mp + (size_t)e * 512 * NT);

    // tA = A^T m  (4x6)
    float ta[4][6];
    #pragma unroll
    for (int j = 0; j < 6; j++) {
        const float m1 = m[6 + j], m2 = m[12 + j], m3 = m[18 + j], m4 = m[24 + j];
        ta[0][j] = m[j] + m1 + m2 + m3 + m4;
        ta[1][j] = m1 - m2 + 2.f * (m3 - m4);
        ta[2][j] = m1 + m2 + 4.f * (m3 + m4);
        ta[3][j] = m1 - m2 + 8.f * (m3 - m4) + m[30 + j];
    }

    const float sc = bng[co] * rsqrtf(bnv[co] + 1e-5f);
    const float sh = (cbias[co] - bnm[co]) * sc + bnb[co];

    const int bn = tau >> 8;
    const int ty = (tau >> 4) & 15;
    const int tx = tau & 15;
    const size_t base = ((size_t)(bn * HIDC + co)) * PIX + (4 * ty) * HW + 4 * tx;

    #pragma unroll
    for (int i = 0; i < 4; i++) {
        const float t1 = ta[i][1], t2 = ta[i][2], t3 = ta[i][3], t4 = ta[i][4];
        float o[4];
        o[0] = ta[i][0] + t1 + t2 + t3 + t4;
        o[1] = t1 - t2 + 2.f * (t3 - t4);
        o[2] = t1 + t2 + 4.f * (t3 + t4);
        o[3] = t1 - t2 + 8.f * (t3 - t4) + ta[i][5];
        #pragma unroll
        for (int j = 0; j < 4; j++) o[j] = fmaxf(fmaf(o[j], sc, sh), 0.f);

        if (OUTH) {
            __half* op = (__half*)outv + base + i * HW;
            __half2 h01 = __floats2half2_rn(o[0], o[1]);
            __half2 h23 = __floats2half2_rn(o[2], o[3]);
            uint2 pk;
            pk.x = *reinterpret_cast<uint32_t*>(&h01);
            pk.y = *reinterpret_cast<uint32_t*>(&h23);
            *(uint2*)op = pk;
        } else {
            float* op = (float*)outv + base + i * HW;
            *(float4*)op = make_float4(o[0], o[1], o[2], o[3]);
        }
    }
}

// ---------------- adaptive avg pool 64x64 -> 4x4 ----------------------------
__global__ void pool_kernel(float* __restrict__ feat)
{
    const int nc = blockIdx.x;
    const int n  = nc >> 9;
    const int c  = nc & 511;
    const float* p = g_act2 + (size_t)nc * PIX;
    const int t = threadIdx.x;
    const int q = t >> 4, r = t & 15;
    const int qh = q >> 2, qw = q & 3;
    const float* row = p + (qh * 16 + r) * HW + qw * 16;
    float s = 0.f;
    #pragma unroll
    for (int j = 0; j < 16; j++) s += row[j];
    __shared__ float part[256];
    part[t] = s;
    __syncthreads();
    if (t < 16) {
        float acc = 0.f;
        #pragma unroll
        for (int j = 0; j < 16; j++) acc += part[t * 16 + j];
        feat[n * FLAT + c * 16 + t] = acc * (1.f / 256.f);
    }
}

// ---------------- clinical embedding (4 -> 128) -----------------------------
__global__ void clin_kernel(const float* __restrict__ x, const float* __restrict__ w,
                            const float* __restrict__ b, float* __restrict__ feat)
{
    const int n = blockIdx.x;
    const int j = threadIdx.x;
    float s = b[j];
    #pragma unroll
    for (int i = 0; i < 4; i++) s = fmaf(w[j * 4 + i], x[n * 4 + i], s);
    feat[n * FLAT + 8192 + j] = s;
}

// ---------------- generic linear: warp per (n, o) ---------------------------
__global__ void linear_kernel(const float* __restrict__ in, const float* __restrict__ w,
                              const float* __restrict__ b, float* __restrict__ out,
                              int In, int Out, int act)
{
    const int gw   = (blockIdx.x * blockDim.x + threadIdx.x) >> 5;
    const int lane = threadIdx.x & 31;
    if (gw >= 16 * Out) return;
    const int o = gw >> 4;
    const int n = gw & 15;
    const float* wr = w + (size_t)o * In;
    const float* xr = in + (size_t)n * In;
    float s = 0.f;
    for (int i = lane; i < In; i += 32) s = fmaf(wr[i], xr[i], s);
    #pragma unroll
    for (int off = 16; off; off >>= 1) s += __shfl_xor_sync(0xFFFFFFFFu, s, off);
    if (lane == 0) {
        s += b[o];
        if (act == 1)      s = fmaxf(s, 0.f);
        else if (act == 2) s = 1.f / (1.f + expf(-s));
        else if (act == 3) s = fminf(fmaxf(s, -5.f), 0.f);
        out[n * Out + o] = s;
    }
}

// ---------------- sampling head ---------------------------------------------
__global__ void head_kernel(const float* __restrict__ noise, const float* __restrict__ u,
                            float* __restrict__ out)
{
    const int t = threadIdx.x;
    if (t >= 48) return;
    const int n = t / 3, k = t % 3;
    const int nk = n * 3 + k;
    float pm[4], ls[4], p[4];
    float lp = 0.f;
    #pragma unroll
    for (int j = 0; j < 4; j++) {
        pm[j] = g_pm[n * 12 + k * 4 + j];
        ls[j] = g_ls[n * 12 + k * 4 + j];
        const float sd = expf(ls[j]);
        p[j] = pm[j] + noise[nk * 4 + j] * sd;
        const float z = (p[j] - pm[j]) / sd;
        lp += z * z + 2.f * ls[j];
    }
    lp *= -0.5f;
    #pragma unroll
    for (int j = 0; j < 4; j++) p[j] = fminf(fmaxf(p[j], 0.f), 1.f);
    const float cx = p[0], cy = p[1];
    const float s2 = p[2] * 0.2f + 0.1f;
    const float s3 = p[3] * 0.2f + 0.1f;
    out[480 + nk] = lp;
    out[528 + nk * 4 + 0] = cx;
    out[528 + nk * 4 + 1] = cy;
    out[528 + nk * 4 + 2] = s2;
    out[528 + nk * 4 + 3] = s3;
    #pragma unroll
    for (int pt = 0; pt < 5; pt++) {
        const float ux = u[(nk * 5 + pt) * 2 + 0];
        const float uy = u[(nk * 5 + pt) * 2 + 1];
        float px = (cx + (ux - 0.5f) * s2) * 256.f;
        float py = (cy + (uy - 0.5f) * s3) * 256.f;
        px = fminf(fmaxf(px, 0.f), 255.f);
        py = fminf(fmaxf(py, 0.f), 255.f);
        out[(n * 15 + k * 5 + pt) * 2 + 0] = px;
        out[(n * 15 + k * 5 + pt) * 2 + 1] = py;
    }
}

// ---------------- launcher ---------------------------------------------------
extern "C" void kernel_launch(void* const* d_in, const int* in_sizes, int n_in,
                              void* d_out, int out_size)
{
    const float* img   = (const float*)d_in[0];
    const float* clin  = (const float*)d_in[1];
    const float* noise = (const float*)d_in[2];
    const float* u     = (const float*)d_in[3];
    const float* c1w = (const float*)d_in[4];
    const float* c1b = (const float*)d_in[5];
    const float* b1g = (const float*)d_in[6];
    const float* b1b = (const float*)d_in[7];
    const float* b1m = (const float*)d_in[8];
    const float* b1v = (const float*)d_in[9];
    const float* c2w = (const float*)d_in[10];
    const float* c2b = (const float*)d_in[11];
    const float* b2g = (const float*)d_in[12];
    const float* b2b = (const float*)d_in[13];
    const float* b2m = (const float*)d_in[14];
    const float* b2v = (const float*)d_in[15];
    const float* clw = (const float*)d_in[16];
    const float* clb = (const float*)d_in[17];
    const float* p1w = (const float*)d_in[18];
    const float* p1b = (const float*)d_in[19];
    const float* p2w = (const float*)d_in[20];
    const float* p2b = (const float*)d_in[21];
    const float* p3w = (const float*)d_in[22];
    const float* p3b = (const float*)d_in[23];
    const float* l1w = (const float*)d_in[24];
    const float* l1b = (const float*)d_in[25];
    const float* l2w = (const float*)d_in[26];
    const float* l2b = (const float*)d_in[27];

    __half *U1, *U2, *V1, *V2, *act1h;
    float *Mm, *act2, *feat, *h1, *h2, *g1, *pm, *ls;
    cudaGetSymbolAddress((void**)&U1,    g_U1);
    cudaGetSymbolAddress((void**)&U2,    g_U2);
    cudaGetSymbolAddress((void**)&V1,    g_V1);
    cudaGetSymbolAddress((void**)&V2,    g_V2);
    cudaGetSymbolAddress((void**)&Mm,    g_M);
    cudaGetSymbolAddress((void**)&act1h, g_act1h);
    cudaGetSymbolAddress((void**)&act2,  g_act2);
    cudaGetSymbolAddress((void**)&feat,  g_feat);
    cudaGetSymbolAddress((void**)&h1,    g_h1);
    cudaGetSymbolAddress((void**)&h2,    g_h2);
    cudaGetSymbolAddress((void**)&g1,    g_g1);
    cudaGetSymbolAddress((void**)&pm,    g_pm);
    cudaGetSymbolAddress((void**)&ls,    g_ls);

    const int gsmem = 61440;
    cudaFuncSetAttribute(wgemm<256>, cudaFuncAttributeMaxDynamicSharedMemorySize, gsmem);
    cudaFuncSetAttribute(wgemm<512>, cudaFuncAttributeMaxDynamicSharedMemorySize, gsmem);

    // ---- conv1 (Winograd F(4,3)) ----
    wt43<256><<<512, 256>>>(c1w, U1);
    wino_in43<float, 256><<<dim3(8, 256), 256>>>(img, V1);
    wgemm<256><<<dim3(4, 16, 36), 256, gsmem>>>(U1, V1, Mm);
    wout43<true><<<8192, 256>>>(Mm, c1b, b1g, b1b, b1m, b1v, act1h);

    // ---- conv2 (Winograd F(4,3)) ----
    wt43<512><<<1024, 256>>>(c2w, U2);
    wino_in43<__half, 512><<<dim3(16, 256), 256>>>(act1h, V2);
    wgemm<512><<<dim3(4, 16, 36), 256, gsmem>>>(U2, V2, Mm);
    wout43<false><<<8192, 256>>>(Mm, c2b, b2g, b2b, b2m, b2v, act2);

    // ---- tail ----
    pool_kernel<<<BATCH * HIDC, 256>>>(feat);
    clin_kernel<<<BATCH, 128>>>(clin, clw, clb, feat);

    linear_kernel<<<(16 * 512 + 7) / 8, 256>>>(feat, p1w, p1b, h1, FLAT, 512, 1);
    linear_kernel<<<(16 * 256 + 7) / 8, 256>>>(h1,   p2w, p2b, h2, 512,  256, 1);
    linear_kernel<<<(16 * 12  + 7) / 8, 256>>>(h2,   p3w, p3b, pm, 256,  12,  2);
    linear_kernel<<<(16 * 256 + 7) / 8, 256>>>(feat, l1w, l1b, g1, FLAT, 256, 1);
    linear_kernel<<<(16 * 12  + 7) / 8, 256>>>(g1,   l2w, l2b, ls, 256,  12,  3);

    head_kernel<<<1, 64>>>(noise, u, (float*)d_out);
}